// round 8
// baseline (speedup 1.0000x reference)
#include <cuda_runtime.h>
#include <cuda.h>
#include <cuda_fp16.h>
#include <cstdint>

#define BSZ   1024
#define LSEQ  200
#define CCH   80
#define OOUT  30
#define ROWS_TOT (BSZ * LSEQ)      // 204800
#define NCOL  240
#define KDIM  300
#define KSTR  320                  // zero-padded K for fp16 W
#define BN    120                  // N per CTA
#define NCHUNK 10                  // K=304 effective (chunk 9: 1 k-step)
#define NCTA  1626
#define NTHR  384
#define ABYTES 16384               // A stage: 128 rows x 32f (128B rows, SW128)
#define BBLK  15360                // B block: 120 rows x 64h (128B rows, SW128)
#define NBBLK 5
#define BOFF  (3 * ABYTES)         // 49152
#define BTOT  (NBBLK * BBLK)       // 76800
#define SMEM_DYN (BOFF + BTOT + 1024)  // + align slack
#define DSS   121

__device__ int    g_h[2][BSZ * CCH];
__device__ __half g_wh[2][NCOL * KSTR];

// ---------------- PTX helpers ----------------
__device__ __forceinline__ uint32_t smem_u32(const void* p) {
    uint32_t a;
    asm("{ .reg .u64 t; cvta.to.shared.u64 t, %1; cvt.u32.u64 %0, t; }" : "=r"(a) : "l"(p));
    return a;
}
#define MBAR_INIT(a, c) asm volatile("mbarrier.init.shared.b64 [%0], %1;" :: "r"(a), "r"(c) : "memory")
#define MBAR_EXPECT(a, b) asm volatile("mbarrier.arrive.expect_tx.shared.b64 _, [%0], %1;" :: "r"(a), "r"(b) : "memory")
#define MBAR_WAIT(a, ph) do { \
    uint32_t _m = (a), _p = (ph), _d; \
    asm volatile("{\n\t.reg .pred p;\n\t" \
        "mbarrier.try_wait.parity.acquire.cta.shared::cta.b64 p, [%1], %2;\n\t" \
        "selp.b32 %0, 1, 0, p;\n\t}" : "=r"(_d) : "r"(_m), "r"(_p) : "memory"); \
    if (!_d) { \
        asm volatile("{\n\t.reg .pred P1;\n\tWL_%=:\n\t" \
            "mbarrier.try_wait.parity.acquire.cta.shared::cta.b64 P1, [%0], %1, 0x989680;\n\t" \
            "@P1 bra.uni WD_%=;\n\tbra.uni WL_%=;\n\tWD_%=:\n\t}" \
            :: "r"(_m), "r"(_p) : "memory"); \
    } } while (0)

__device__ __forceinline__ void tma2d(uint32_t dst, const CUtensorMap* m, int x, int y, uint32_t mb) {
    asm volatile("cp.async.bulk.tensor.2d.shared::cta.global.tile.mbarrier::complete_tx::bytes "
                 "[%0], [%1, {%2, %3}], [%4];" :: "r"(dst), "l"(m), "r"(x), "r"(y), "r"(mb) : "memory");
}
__device__ __forceinline__ float2 lds64(uint32_t a) {
    float2 v;
    asm volatile("ld.shared.v2.f32 {%0,%1}, [%2];" : "=f"(v.x), "=f"(v.y) : "r"(a));
    return v;
}
__device__ __forceinline__ uint32_t packh2(float lo, float hi) {
    uint32_t r;
    asm("cvt.rn.f16x2.f32 %0, %1, %2;" : "=r"(r) : "f"(hi), "f"(lo));
    return r;
}
__device__ __forceinline__ void ldsm4(uint32_t* r, uint32_t addr) {
    asm volatile("ldmatrix.sync.aligned.m8n8.x4.shared.b16 {%0,%1,%2,%3}, [%4];"
                 : "=r"(r[0]), "=r"(r[1]), "=r"(r[2]), "=r"(r[3]) : "r"(addr));
}
__device__ __forceinline__ void ldsm2(uint32_t* r, uint32_t addr) {
    asm volatile("ldmatrix.sync.aligned.m8n8.x2.shared.b16 {%0,%1}, [%2];"
                 : "=r"(r[0]), "=r"(r[1]) : "r"(addr));
}
__device__ __forceinline__ void mma16h(uint32_t* c, const uint32_t* a, uint32_t b0, uint32_t b1) {
    asm volatile("mma.sync.aligned.m16n8k16.row.col.f16.f16.f16.f16 "
                 "{%0,%1}, {%2,%3,%4,%5}, {%6,%7}, {%0,%1};"
                 : "+r"(c[0]), "+r"(c[1])
                 : "r"(a[0]), "r"(a[1]), "r"(a[2]), "r"(a[3]), "r"(b0), "r"(b1));
}

// ---------------- kernels ----------------
__global__ void nop_kernel() {}

__global__ void prep_kernel(const float* __restrict__ w1, const float* __restrict__ w2) {
    const int i = blockIdx.x * blockDim.x + threadIdx.x;   // 163840
    ((int*)g_h)[i] = 0;
    if (i < NCOL * KSTR) {
        const int row = i / KSTR, col = i % KSTR;
        g_wh[0][i] = __float2half_rn((col < KDIM) ? w1[row * KDIM + col] : 0.f);
        g_wh[1][i] = __float2half_rn((col < KDIM) ? w2[row * KDIM + col] : 0.f);
    }
}

__global__ void __launch_bounds__(NTHR, 1) gemm_conv_kernel(
    const __grid_constant__ CUtensorMap xm1, const __grid_constant__ CUtensorMap xm2,
    const __grid_constant__ CUtensorMap wm1, const __grid_constant__ CUtensorMap wm2,
    const float* __restrict__ b1, const float* __restrict__ b2)
{
    extern __shared__ char dynsm[];
    __shared__ __align__(8) unsigned long long mb_full[3], mb_b;

    const int tid = threadIdx.x, wid = tid >> 5, lane = tid & 31;
    const int grp = lane >> 2, tig = lane & 3;
    const int warp_m = wid & 3, warp_n = wid >> 2;   // 4M x 3N, warp tile 32x40
    const int sub = blockIdx.z;
    const int nbase = blockIdx.y * BN;
    const float* bc = sub ? b2 : b1;
    const CUtensorMap* xm = sub ? &xm2 : &xm1;
    const CUtensorMap* wm = sub ? &wm2 : &wm1;
    const int r0 = blockIdx.x * 126;

    const uint32_t raw = smem_u32(dynsm);
    const uint32_t sb = (raw + 1023u) & ~1023u;      // 1024-aligned base
    char* dptr = dynsm + (sb - raw);

    if (tid == 0) {
        MBAR_INIT(smem_u32(&mb_full[0]), 1);
        MBAR_INIT(smem_u32(&mb_full[1]), 1);
        MBAR_INIT(smem_u32(&mb_full[2]), 1);
        MBAR_INIT(smem_u32(&mb_b), 1);
        asm volatile("fence.proxy.async.shared::cta;" ::: "memory");
    }
    __syncthreads();

    if (tid == 0) {
        MBAR_EXPECT(smem_u32(&mb_b), BTOT);
        #pragma unroll
        for (int j = 0; j < NBBLK; j++)
            tma2d(sb + BOFF + j * BBLK, wm, j * 64, nbase, smem_u32(&mb_b));
        MBAR_EXPECT(smem_u32(&mb_full[0]), ABYTES);
        tma2d(sb, xm, 0, r0, smem_u32(&mb_full[0]));
        MBAR_EXPECT(smem_u32(&mb_full[1]), ABYTES);
        tma2d(sb + ABYTES, xm, 32, r0, smem_u32(&mb_full[1]));
    }

    uint32_t acc[2][5][2];
    #pragma unroll
    for (int mt = 0; mt < 2; mt++)
        #pragma unroll
        for (int nt = 0; nt < 5; nt++) { acc[mt][nt][0] = 0u; acc[mt][nt][1] = 0u; }

    const int bmat = lane >> 3;
    const int brow_off4 = ((bmat & 2) << 2) + (lane & 7);
    const int bk_off4 = (bmat & 1) << 3;            // halves
    const int brow_off2 = lane & 7;
    const int bk_off2 = (bmat & 1) << 3;

    MBAR_WAIT(smem_u32(&mb_b), 0);                  // B resident

    for (int c = 0; c < NCHUNK; c++) {
        MBAR_WAIT(smem_u32(&mb_full[c % 3]), (c / 3) & 1);
        __syncthreads();
        if (tid == 0 && c + 2 < NCHUNK) {
            const int s2 = (c + 2) % 3;
            MBAR_EXPECT(smem_u32(&mb_full[s2]), ABYTES);
            tma2d(sb + s2 * ABYTES, xm, (c + 2) * 32, r0, smem_u32(&mb_full[s2]));
        }
        const uint32_t Ab = sb + (c % 3) * ABYTES;
        const uint32_t Bb = sb + BOFF;
        const int ksmax = (c == NCHUNK - 1) ? 1 : 2;
        #pragma unroll
        for (int ks = 0; ks < 2; ks++) {
            if (ks >= ksmax) break;
            const int k0 = ks * 16;                 // floats within chunk
            const int k0abs = c * 32 + k0;
            uint32_t a[2][4];
            #pragma unroll
            for (int mt = 0; mt < 2; mt++) {
                const int row = warp_m * 32 + mt * 16 + grp;   // (row+8)&7 == row&7
                const uint32_t rx = (row & 7) << 4;
                const uint32_t kb = k0 * 4 + tig * 8;
                const float2 p0 = lds64(Ab + row * 128       + (kb ^ rx));
                const float2 p1 = lds64(Ab + (row + 8) * 128 + (kb ^ rx));
                const float2 p2 = lds64(Ab + row * 128       + ((kb + 32) ^ rx));
                const float2 p3 = lds64(Ab + (row + 8) * 128 + ((kb + 32) ^ rx));
                a[mt][0] = packh2(p0.x, p0.y);
                a[mt][1] = packh2(p1.x, p1.y);
                a[mt][2] = packh2(p2.x, p2.y);
                a[mt][3] = packh2(p3.x, p3.y);
            }
            const uint32_t Bjb = Bb + (k0abs >> 6) * BBLK;
            const uint32_t kb2 = (k0abs & 63);      // halves within 64h block
            #pragma unroll
            for (int pair = 0; pair < 2; pair++) {
                const int brow = warp_n * 40 + pair * 16 + brow_off4;
                const uint32_t addr = Bjb + brow * 128 + ((((kb2 + bk_off4) * 2)) ^ ((brow & 7) << 4));
                uint32_t b[4];
                ldsm4(b, addr);
                mma16h(acc[0][2 * pair],     a[0], b[0], b[1]);
                mma16h(acc[1][2 * pair],     a[1], b[0], b[1]);
                mma16h(acc[0][2 * pair + 1], a[0], b[2], b[3]);
                mma16h(acc[1][2 * pair + 1], a[1], b[2], b[3]);
            }
            {
                const int brow = warp_n * 40 + 32 + brow_off2;
                const uint32_t addr = Bjb + brow * 128 + ((((kb2 + bk_off2) * 2)) ^ ((brow & 7) << 4));
                uint32_t b[2];
                ldsm2(b, addr);
                mma16h(acc[0][4], a[0], b[0], b[1]);
                mma16h(acc[1][4], a[1], b[0], b[1]);
            }
        }
    }
    __syncthreads();

    // ---- stage D (128 x 120) into smem ----
    float* ds = (float*)dptr;
    #pragma unroll
    for (int mt = 0; mt < 2; mt++)
        #pragma unroll
        for (int nt = 0; nt < 5; nt++) {
            const int rb = warp_m * 32 + mt * 16 + grp;
            const int n0 = warp_n * 40 + nt * 8 + tig * 2;
            const float2 lo = __half22float2(*(__half2*)&acc[mt][nt][0]);
            const float2 hi = __half22float2(*(__half2*)&acc[mt][nt][1]);
            ds[rb * DSS + n0]           = lo.x;
            ds[rb * DSS + n0 + 1]       = lo.y;
            ds[(rb + 8) * DSS + n0]     = hi.x;
            ds[(rb + 8) * DSS + n0 + 1] = hi.y;
        }
    __syncthreads();

    // ---- 3-tap diagonal combine + bias + relu + segment max + atomicMax ----
    const int bA = r0 / LSEQ;
    const int chbase = blockIdx.y * 40;
    for (int cl = wid; cl < 40; cl += 12) {
        const int ch = chbase + cl;
        const float bias = __ldg(&bc[ch]);
        float mA = 0.f, mB = 0.f;
        #pragma unroll
        for (int k = 0; k < 4; k++) {
            const int i = lane + 32 * k;
            if (i >= 126) continue;
            const int g = r0 + i;
            if (g + 2 >= ROWS_TOT) continue;
            if ((g % LSEQ) > (LSEQ - 3)) continue;
            float v = ds[i * DSS + 3 * cl] + ds[(i + 1) * DSS + 3 * cl + 1]
                    + ds[(i + 2) * DSS + 3 * cl + 2] + bias;
            v = fmaxf(v, 0.f);
            if (g / LSEQ == bA) mA = fmaxf(mA, v); else mB = fmaxf(mB, v);
        }
        #pragma unroll
        for (int off = 16; off; off >>= 1) {
            mA = fmaxf(mA, __shfl_xor_sync(0xffffffffu, mA, off));
            mB = fmaxf(mB, __shfl_xor_sync(0xffffffffu, mB, off));
        }
        if (lane == 0) {
            if (mA > 0.f) atomicMax(&g_h[sub][bA * CCH + ch], __float_as_int(mA));
            if (mB > 0.f && bA + 1 < BSZ)
                atomicMax(&g_h[sub][(bA + 1) * CCH + ch], __float_as_int(mB));
        }
    }
}

__global__ void __launch_bounds__(256) finish_kernel(
    const float* __restrict__ wfc1, const float* __restrict__ bfc1,
    const float* __restrict__ wfc2, const float* __restrict__ bfc2,
    float* __restrict__ out)
{
    const int wid = threadIdx.x >> 5, j = threadIdx.x & 31;
    const int b = blockIdx.x * 8 + wid;
    float p = 0.f;
    if (j < OOUT) {
        float s1 = bfc1[j], s2 = bfc2[j];
        const int* h1 = &g_h[0][b * CCH];
        const int* h2 = &g_h[1][b * CCH];
        #pragma unroll 8
        for (int c = 0; c < CCH; c++) {
            s1 += __int_as_float(h1[c]) * wfc1[j * CCH + c];
            s2 += __int_as_float(h2[c]) * wfc2[j * CCH + c];
        }
        p = fmaxf(s1, 0.f) * fmaxf(s2, 0.f);
    }
    #pragma unroll
    for (int off = 16; off; off >>= 1) p += __shfl_xor_sync(0xffffffffu, p, off);
    if (j == 0) out[b] = p;
}

// ---------------- host ----------------
typedef CUresult (*EncodeFn)(CUtensorMap*, CUtensorMapDataType, cuuint32_t, void*,
                             const cuuint64_t*, const cuuint64_t*, const cuuint32_t*, const cuuint32_t*,
                             CUtensorMapInterleave, CUtensorMapSwizzle, CUtensorMapL2promotion,
                             CUtensorMapFloatOOBfill);

static void enc2d(EncodeFn f, CUtensorMap* m, void* p, CUtensorMapDataType dt,
                  cuuint64_t d0, cuuint64_t d1, cuuint64_t strideB,
                  cuuint32_t b0, cuuint32_t b1) {
    cuuint64_t gd[2] = {d0, d1};
    cuuint64_t gs[1] = {strideB};
    cuuint32_t bx[2] = {b0, b1};
    cuuint32_t es[2] = {1, 1};
    f(m, dt, 2, p, gd, gs, bx, es,
      CU_TENSOR_MAP_INTERLEAVE_NONE, CU_TENSOR_MAP_SWIZZLE_128B,
      CU_TENSOR_MAP_L2_PROMOTION_L2_128B, CU_TENSOR_MAP_FLOAT_OOB_FILL_NONE);
}

extern "C" void kernel_launch(void* const* d_in, const int* in_sizes, int n_in,
                              void* d_out, int out_size) {
    static EncodeFn enc = nullptr;
    static void* whp = nullptr;
    if (!enc) {
        cudaFuncSetAttribute(gemm_conv_kernel,
                             cudaFuncAttributeMaxDynamicSharedMemorySize, SMEM_DYN);
        void* fn = nullptr;
        cudaDriverEntryPointQueryResult qst;
        cudaGetDriverEntryPointByVersion("cuTensorMapEncodeTiled", &fn, 12000,
                                         cudaEnableDefault, &qst);
        enc = (EncodeFn)fn;
        cudaGetSymbolAddress(&whp, g_wh);
    }
    CUtensorMap xm1, xm2, wm1, wm2;
    enc2d(enc, &xm1, (void*)d_in[0], CU_TENSOR_MAP_DATA_TYPE_FLOAT32,
          KDIM, ROWS_TOT, KDIM * 4, 32, 128);
    enc2d(enc, &xm2, (void*)d_in[1], CU_TENSOR_MAP_DATA_TYPE_FLOAT32,
          KDIM, ROWS_TOT, KDIM * 4, 32, 128);
    enc2d(enc, &wm1, whp, CU_TENSOR_MAP_DATA_TYPE_FLOAT16,
          KSTR, NCOL, KSTR * 2, 64, BN);
    enc2d(enc, &wm2, (char*)whp + NCOL * KSTR * 2, CU_TENSOR_MAP_DATA_TYPE_FLOAT16,
          KSTR, NCOL, KSTR * 2, 64, BN);

    prep_kernel<<<160, 1024>>>((const float*)d_in[2], (const float*)d_in[6]);
    nop_kernel<<<1, 32>>>();
    nop_kernel<<<1, 32>>>();
    gemm_conv_kernel<<<dim3(NCTA, 2, 2), NTHR, SMEM_DYN>>>(
        xm1, xm2, wm1, wm2, (const float*)d_in[3], (const float*)d_in[7]);
    finish_kernel<<<BSZ / 8, 256>>>((const float*)d_in[4], (const float*)d_in[5],
                                    (const float*)d_in[8], (const float*)d_in[9],
                                    (float*)d_out);
}

// round 9
// speedup vs baseline: 1.4444x; 1.4444x over previous
#include <cuda_runtime.h>
#include <cuda.h>
#include <cuda_fp16.h>
#include <cstdint>

#define BSZ   1024
#define LSEQ  200
#define CCH   80
#define OOUT  30
#define ROWS_TOT (BSZ * LSEQ)      // 204800
#define NCOL  240
#define KDIM  300
#define KSTR  320                  // zero-padded K for fp16 W in gmem
#define BN    120                  // N per CTA (2 CTAs cover 240)
#define NCHUNK 19                  // K chunks of 16 -> 304 (TMA zero-fills 300..303)
#define NCTA  1626
#define NTHR  384
#define ASTG  8192                 // A TMA stage: 128 rows x 16f, 64B rows (SW64)
#define APRIME_OFF (2 * ASTG)      // 16384: A' fp16 128 x 16h, stride 80B
#define APRIME_BYTES (128 * 80)    // 10240
#define B_OFF (APRIME_OFF + APRIME_BYTES)   // 26624
#define BSTRIDE 624                // B row stride bytes (312 halves), 39 units -> conflict-free
#define B_BYTES (BN * BSTRIDE)     // 74880
#define SMEM_DYN (B_OFF + B_BYTES + 1024)   // 102528 -> 2 CTAs/SM
#define DSS   121

__device__ int    g_h[2][BSZ * CCH];
__device__ __half g_wh[2][NCOL * KSTR];

// ---------------- PTX helpers ----------------
__device__ __forceinline__ uint32_t smem_u32(const void* p) {
    uint32_t a;
    asm("{ .reg .u64 t; cvta.to.shared.u64 t, %1; cvt.u32.u64 %0, t; }" : "=r"(a) : "l"(p));
    return a;
}
#define MBAR_INIT(a, c) asm volatile("mbarrier.init.shared.b64 [%0], %1;" :: "r"(a), "r"(c) : "memory")
#define MBAR_EXPECT(a, b) asm volatile("mbarrier.arrive.expect_tx.shared.b64 _, [%0], %1;" :: "r"(a), "r"(b) : "memory")
#define MBAR_WAIT(a, ph) do { \
    uint32_t _m = (a), _p = (ph), _d; \
    asm volatile("{\n\t.reg .pred p;\n\t" \
        "mbarrier.try_wait.parity.acquire.cta.shared::cta.b64 p, [%1], %2;\n\t" \
        "selp.b32 %0, 1, 0, p;\n\t}" : "=r"(_d) : "r"(_m), "r"(_p) : "memory"); \
    if (!_d) { \
        asm volatile("{\n\t.reg .pred P1;\n\tWL_%=:\n\t" \
            "mbarrier.try_wait.parity.acquire.cta.shared::cta.b64 P1, [%0], %1, 0x989680;\n\t" \
            "@P1 bra.uni WD_%=;\n\tbra.uni WL_%=;\n\tWD_%=:\n\t}" \
            :: "r"(_m), "r"(_p) : "memory"); \
    } } while (0)

__device__ __forceinline__ void tma2d(uint32_t dst, const CUtensorMap* m, int x, int y, uint32_t mb) {
    asm volatile("cp.async.bulk.tensor.2d.shared::cta.global.tile.mbarrier::complete_tx::bytes "
                 "[%0], [%1, {%2, %3}], [%4];" :: "r"(dst), "l"(m), "r"(x), "r"(y), "r"(mb) : "memory");
}
__device__ __forceinline__ void cpa16(uint32_t dst, const void* src) {
    asm volatile("cp.async.cg.shared.global [%0], [%1], 16;" :: "r"(dst), "l"(src) : "memory");
}
#define CP_COMMIT() asm volatile("cp.async.commit_group;" ::: "memory")
#define CP_WAIT0()  asm volatile("cp.async.wait_group 0;" ::: "memory")

__device__ __forceinline__ float4 lds128(uint32_t a) {
    float4 v;
    asm volatile("ld.shared.v4.f32 {%0,%1,%2,%3}, [%4];"
                 : "=f"(v.x), "=f"(v.y), "=f"(v.z), "=f"(v.w) : "r"(a));
    return v;
}
__device__ __forceinline__ void sts64(uint32_t a, uint32_t v0, uint32_t v1) {
    asm volatile("st.shared.v2.b32 [%0], {%1,%2};" :: "r"(a), "r"(v0), "r"(v1) : "memory");
}
__device__ __forceinline__ uint32_t packh2(float lo, float hi) {
    uint32_t r;
    asm("cvt.rn.f16x2.f32 %0, %1, %2;" : "=r"(r) : "f"(hi), "f"(lo));
    return r;
}
__device__ __forceinline__ void ldsm4(uint32_t* r, uint32_t addr) {
    asm volatile("ldmatrix.sync.aligned.m8n8.x4.shared.b16 {%0,%1,%2,%3}, [%4];"
                 : "=r"(r[0]), "=r"(r[1]), "=r"(r[2]), "=r"(r[3]) : "r"(addr));
}
__device__ __forceinline__ void ldsm2(uint32_t* r, uint32_t addr) {
    asm volatile("ldmatrix.sync.aligned.m8n8.x2.shared.b16 {%0,%1}, [%2];"
                 : "=r"(r[0]), "=r"(r[1]) : "r"(addr));
}
__device__ __forceinline__ void mma16h(uint32_t* c, const uint32_t* a, uint32_t b0, uint32_t b1) {
    asm volatile("mma.sync.aligned.m16n8k16.row.col.f16.f16.f16.f16 "
                 "{%0,%1}, {%2,%3,%4,%5}, {%6,%7}, {%0,%1};"
                 : "+r"(c[0]), "+r"(c[1])
                 : "r"(a[0]), "r"(a[1]), "r"(a[2]), "r"(a[3]), "r"(b0), "r"(b1));
}

// ---------------- kernels ----------------
__global__ void nop_kernel() {}

__global__ void prep_kernel(const float* __restrict__ w1, const float* __restrict__ w2) {
    const int i = blockIdx.x * blockDim.x + threadIdx.x;   // 163840
    ((int*)g_h)[i] = 0;
    if (i < NCOL * KSTR) {
        const int row = i / KSTR, col = i % KSTR;
        g_wh[0][i] = __float2half_rn((col < KDIM) ? w1[row * KDIM + col] : 0.f);
        g_wh[1][i] = __float2half_rn((col < KDIM) ? w2[row * KDIM + col] : 0.f);
    }
}

__global__ void __launch_bounds__(NTHR, 2) gemm_conv_kernel(
    const __grid_constant__ CUtensorMap xm1, const __grid_constant__ CUtensorMap xm2,
    const float* __restrict__ b1, const float* __restrict__ b2)
{
    extern __shared__ char dynsm[];
    __shared__ __align__(8) unsigned long long mb_full[2];

    const int tid = threadIdx.x, wid = tid >> 5, lane = tid & 31;
    const int warp_m = wid & 3, warp_n = wid >> 2;   // 4M x 3N, warp tile 32x40
    const int nsplit = blockIdx.x & 1;
    const int sub = blockIdx.x >> 1;
    const int nbase = nsplit * BN;
    const float* bc = sub ? b2 : b1;
    const CUtensorMap* xm = sub ? &xm2 : &xm1;
    const __half* Wh = g_wh[sub];
    const int r0 = blockIdx.y * 126;

    const uint32_t raw = smem_u32(dynsm);
    const uint32_t sb = (raw + 1023u) & ~1023u;
    char* dptr = dynsm + (sb - raw);
    const uint32_t Ap = sb + APRIME_OFF;
    const uint32_t Bb = sb + B_OFF;

    if (tid == 0) {
        MBAR_INIT(smem_u32(&mb_full[0]), 1);
        MBAR_INIT(smem_u32(&mb_full[1]), 1);
        asm volatile("fence.proxy.async.shared::cta;" ::: "memory");
        MBAR_EXPECT(smem_u32(&mb_full[0]), ASTG);
        tma2d(sb,        xm, 0,  r0, smem_u32(&mb_full[0]));
        MBAR_EXPECT(smem_u32(&mb_full[1]), ASTG);
        tma2d(sb + ASTG, xm, 16, r0, smem_u32(&mb_full[1]));
    }

    // ---- B resident load (once): 120 rows x 39 16B-units ----
    #pragma unroll
    for (int it = 0; it < 13; it++) {
        const int idx = tid + it * NTHR;
        if (idx < BN * 39) {
            const int row = idx / 39, u = idx % 39;
            cpa16(Bb + row * BSTRIDE + u * 16, Wh + (nbase + row) * KSTR + u * 8);
        }
    }
    CP_COMMIT();
    CP_WAIT0();
    __syncthreads();                                 // B + mbar init visible

    uint32_t acc[2][5][2];
    #pragma unroll
    for (int mt = 0; mt < 2; mt++)
        #pragma unroll
        for (int nt = 0; nt < 5; nt++) { acc[mt][nt][0] = 0u; acc[mt][nt][1] = 0u; }

    // fragment lane addressing
    const int l15 = lane & 15, lhi = lane >> 4;
    const int bmat = lane >> 3;
    const int brow_off4 = ((bmat & 2) << 2) + (lane & 7);
    const int bk_off4 = (bmat & 1) << 3;             // halves
    const int brow_off2 = lane & 7;
    const int bk_off2 = (bmat & 1) << 3;

    for (int c = 0; c < NCHUNK; c++) {
        const int s = c & 1;
        MBAR_WAIT(smem_u32(&mb_full[s]), (c >> 1) & 1);

        // ---- cooperative convert: stage s (fp32 SW64) -> A' (fp16, 80B rows) ----
        const uint32_t As = sb + s * ASTG;
        #pragma unroll
        for (int it = 0; it < 2; it++) {
            const int u = tid + it * NTHR;           // 512 16B-units
            if (u < 512) {
                const int row = u >> 2, v = u & 3;
                const float4 f = lds128(As + row * 64 + ((v * 16) ^ ((row & 6) << 3)));
                sts64(Ap + row * 80 + v * 8, packh2(f.x, f.y), packh2(f.z, f.w));
            }
        }
        __syncthreads();                             // A' ready; stage s free
        if (tid == 0 && c + 2 < NCHUNK) {
            MBAR_EXPECT(smem_u32(&mb_full[s]), ASTG);
            tma2d(sb + s * ASTG, xm, (c + 2) * 16, r0, smem_u32(&mb_full[s]));
        }

        // ---- compute one k16 step ----
        uint32_t a[2][4];
        #pragma unroll
        for (int mt = 0; mt < 2; mt++)
            ldsm4(a[mt], Ap + (warp_m * 32 + mt * 16 + l15) * 80 + lhi * 16);

        const uint32_t kbyte = c * 32;               // k0abs * 2 bytes
        #pragma unroll
        for (int pair = 0; pair < 2; pair++) {
            const int brow = warp_n * 40 + pair * 16 + brow_off4;
            uint32_t b[4];
            ldsm4(b, Bb + brow * BSTRIDE + kbyte + bk_off4 * 2);
            mma16h(acc[0][2 * pair],     a[0], b[0], b[1]);
            mma16h(acc[1][2 * pair],     a[1], b[0], b[1]);
            mma16h(acc[0][2 * pair + 1], a[0], b[2], b[3]);
            mma16h(acc[1][2 * pair + 1], a[1], b[2], b[3]);
        }
        {
            const int brow = warp_n * 40 + 32 + brow_off2;
            uint32_t b[2];
            ldsm2(b, Bb + brow * BSTRIDE + kbyte + bk_off2 * 2);
            mma16h(acc[0][4], a[0], b[0], b[1]);
            mma16h(acc[1][4], a[1], b[0], b[1]);
        }
        __syncthreads();                             // protect A' for next convert
    }

    // ---- stage D (128 x 120) into smem ----
    const int grp = lane >> 2, tig = lane & 3;
    float* ds = (float*)dptr;
    #pragma unroll
    for (int mt = 0; mt < 2; mt++)
        #pragma unroll
        for (int nt = 0; nt < 5; nt++) {
            const int rb = warp_m * 32 + mt * 16 + grp;
            const int n0 = warp_n * 40 + nt * 8 + tig * 2;
            const float2 lo = __half22float2(*(__half2*)&acc[mt][nt][0]);
            const float2 hi = __half22float2(*(__half2*)&acc[mt][nt][1]);
            ds[rb * DSS + n0]           = lo.x;
            ds[rb * DSS + n0 + 1]       = lo.y;
            ds[(rb + 8) * DSS + n0]     = hi.x;
            ds[(rb + 8) * DSS + n0 + 1] = hi.y;
        }
    __syncthreads();

    // ---- 3-tap diagonal combine + bias + relu + segment max + atomicMax ----
    const int bA = r0 / LSEQ;
    const int chbase = nsplit * 40;
    for (int cl = wid; cl < 40; cl += 12) {
        const int ch = chbase + cl;
        const float bias = __ldg(&bc[ch]);
        float mA = 0.f, mB = 0.f;
        #pragma unroll
        for (int k = 0; k < 4; k++) {
            const int i = lane + 32 * k;
            if (i >= 126) continue;
            const int g = r0 + i;
            if (g + 2 >= ROWS_TOT) continue;
            if ((g % LSEQ) > (LSEQ - 3)) continue;
            float v = ds[i * DSS + 3 * cl] + ds[(i + 1) * DSS + 3 * cl + 1]
                    + ds[(i + 2) * DSS + 3 * cl + 2] + bias;
            v = fmaxf(v, 0.f);
            if (g / LSEQ == bA) mA = fmaxf(mA, v); else mB = fmaxf(mB, v);
        }
        #pragma unroll
        for (int off = 16; off; off >>= 1) {
            mA = fmaxf(mA, __shfl_xor_sync(0xffffffffu, mA, off));
            mB = fmaxf(mB, __shfl_xor_sync(0xffffffffu, mB, off));
        }
        if (lane == 0) {
            if (mA > 0.f) atomicMax(&g_h[sub][bA * CCH + ch], __float_as_int(mA));
            if (mB > 0.f && bA + 1 < BSZ)
                atomicMax(&g_h[sub][(bA + 1) * CCH + ch], __float_as_int(mB));
        }
    }
}

__global__ void __launch_bounds__(256) finish_kernel(
    const float* __restrict__ wfc1, const float* __restrict__ bfc1,
    const float* __restrict__ wfc2, const float* __restrict__ bfc2,
    float* __restrict__ out)
{
    const int wid = threadIdx.x >> 5, j = threadIdx.x & 31;
    const int b = blockIdx.x * 8 + wid;
    float p = 0.f;
    if (j < OOUT) {
        float s1 = bfc1[j], s2 = bfc2[j];
        const int* h1 = &g_h[0][b * CCH];
        const int* h2 = &g_h[1][b * CCH];
        #pragma unroll 8
        for (int c = 0; c < CCH; c++) {
            s1 += __int_as_float(h1[c]) * wfc1[j * CCH + c];
            s2 += __int_as_float(h2[c]) * wfc2[j * CCH + c];
        }
        p = fmaxf(s1, 0.f) * fmaxf(s2, 0.f);
    }
    #pragma unroll
    for (int off = 16; off; off >>= 1) p += __shfl_xor_sync(0xffffffffu, p, off);
    if (j == 0) out[b] = p;
}

// ---------------- host ----------------
typedef CUresult (*EncodeFn)(CUtensorMap*, CUtensorMapDataType, cuuint32_t, void*,
                             const cuuint64_t*, const cuuint64_t*, const cuuint32_t*, const cuuint32_t*,
                             CUtensorMapInterleave, CUtensorMapSwizzle, CUtensorMapL2promotion,
                             CUtensorMapFloatOOBfill);

static void encX(EncodeFn f, CUtensorMap* m, void* p) {
    cuuint64_t gd[2] = {KDIM, ROWS_TOT};
    cuuint64_t gs[1] = {KDIM * 4};
    cuuint32_t bx[2] = {16, 128};
    cuuint32_t es[2] = {1, 1};
    f(m, CU_TENSOR_MAP_DATA_TYPE_FLOAT32, 2, p, gd, gs, bx, es,
      CU_TENSOR_MAP_INTERLEAVE_NONE, CU_TENSOR_MAP_SWIZZLE_64B,
      CU_TENSOR_MAP_L2_PROMOTION_L2_128B, CU_TENSOR_MAP_FLOAT_OOB_FILL_NONE);
}

extern "C" void kernel_launch(void* const* d_in, const int* in_sizes, int n_in,
                              void* d_out, int out_size) {
    static EncodeFn enc = nullptr;
    if (!enc) {
        cudaFuncSetAttribute(gemm_conv_kernel,
                             cudaFuncAttributeMaxDynamicSharedMemorySize, SMEM_DYN);
        void* fn = nullptr;
        cudaDriverEntryPointQueryResult qst;
        cudaGetDriverEntryPointByVersion("cuTensorMapEncodeTiled", &fn, 12000,
                                         cudaEnableDefault, &qst);
        enc = (EncodeFn)fn;
    }
    CUtensorMap xm1, xm2;
    encX(enc, &xm1, (void*)d_in[0]);
    encX(enc, &xm2, (void*)d_in[1]);

    prep_kernel<<<160, 1024>>>((const float*)d_in[2], (const float*)d_in[6]);
    nop_kernel<<<1, 32>>>();
    nop_kernel<<<1, 32>>>();
    gemm_conv_kernel<<<dim3(4, NCTA), NTHR, SMEM_DYN>>>(
        xm1, xm2, (const float*)d_in[3], (const float*)d_in[7]);
    finish_kernel<<<BSZ / 8, 256>>>((const float*)d_in[4], (const float*)d_in[5],
                                    (const float*)d_in[8], (const float*)d_in[9],
                                    (float*)d_out);
}